// round 4
// baseline (speedup 1.0000x reference)
#include <cuda_runtime.h>

// ---------------------------------------------------------------------------
// BatchTopK: out = scatter(top_{k*rows}(relu(x))) over the FLATTENED array.
// R4: single fused full pass. Sampling picks lower bound L; the fused pass
// reads x ONCE, streams zeros to out, and collects all candidates >= L
// (warp-aggregated). Bucket selection, scatter of >bucket values, and exact
// 32-bit refinement all run over the small L2-resident candidate list.
// Full-exact fallback chain (flag-gated no-ops) guarantees correctness if the
// sampled bound under/overshoots.
// ---------------------------------------------------------------------------

#define HIST_BINS 4096
#define CAP1      (1u << 21)   // candidate list: 2M * 8B = 16MB
#define CAP2      (1u << 20)   // in-bucket list: 1M * 8B = 8MB
#define EQ_CAP    2048
#define SSTR4     128          // sample every 128th float4

__device__ unsigned int       g_shist[HIST_BINS];   // sampled histogram
__device__ unsigned int       g_hist[HIST_BINS];    // candidate histogram
__device__ unsigned int       g_fhist[HIST_BINS];   // fallback exact histogram
__device__ unsigned int       g_lbin;
__device__ int                g_bucket;             // -1 keep all positives; HIST_BINS keep none
__device__ unsigned int       g_rem;
__device__ int                g_need_full;
__device__ unsigned int       g_cand_count;
__device__ unsigned int       g_c2_count;
__device__ unsigned long long g_cand[CAP1];         // (bits<<32) | flat_index
__device__ unsigned long long g_cand2[CAP2];

// ---------------------------------------------------------------------------
__global__ void init_kernel() {
    int i = blockIdx.x * blockDim.x + threadIdx.x;
    if (i < HIST_BINS) { g_shist[i] = 0; g_hist[i] = 0; g_fhist[i] = 0; }
    if (i == 0) {
        g_cand_count = 0; g_c2_count = 0; g_bucket = -2; g_rem = 0;
        g_need_full = 0; g_lbin = 0;
    }
}

// ---------------------------------------------------------------------------
__global__ void sample_kernel(const float4* __restrict__ x4, int n4) {
    __shared__ unsigned int sh[HIST_BINS];
    for (int i = threadIdx.x; i < HIST_BINS; i += blockDim.x) sh[i] = 0;
    __syncthreads();
    int ns = n4 / SSTR4;
    int stride = gridDim.x * blockDim.x;
    for (int j = blockIdx.x * blockDim.x + threadIdx.x; j < ns; j += stride) {
        float4 v = x4[(size_t)j * SSTR4];
        if (v.x > 0.f) atomicAdd(&sh[__float_as_uint(v.x) >> 19], 1u);
        if (v.y > 0.f) atomicAdd(&sh[__float_as_uint(v.y) >> 19], 1u);
        if (v.z > 0.f) atomicAdd(&sh[__float_as_uint(v.z) >> 19], 1u);
        if (v.w > 0.f) atomicAdd(&sh[__float_as_uint(v.w) >> 19], 1u);
    }
    __syncthreads();
    for (int i = threadIdx.x; i < HIST_BINS; i += blockDim.x) {
        unsigned c = sh[i];
        if (c) atomicAdd(&g_shist[i], c);
    }
}

// ---------------------------------------------------------------------------
// lbin = largest bin whose sampled suffix count covers ~8x n_keep (clamped to
// half the candidate capacity).
__global__ void choose_kernel(const int* __restrict__ kptr, long long num_samples,
                              int n, int n4) {
    __shared__ unsigned int ssum[1024];
    int t = threadIdx.x;
    unsigned c[4];
#pragma unroll
    for (int q = 0; q < 4; q++) c[q] = g_shist[4 * t + q];
    unsigned my = c[0] + c[1] + c[2] + c[3];
    ssum[t] = my;
    __syncthreads();
    for (int d = 1; d < 1024; d <<= 1) {
        unsigned v = ssum[t] + ((t + d < 1024) ? ssum[t + d] : 0u);
        __syncthreads();
        ssum[t] = v;
        __syncthreads();
    }
    long long n_keep = (long long)kptr[0] * num_samples;
    long long sampled = (long long)(n4 / SSTR4) * 4;
    if (sampled < 1) sampled = 1;
    long long scale = ((long long)n + sampled - 1) / sampled;
    if (scale < 1) scale = 1;
    long long want = 8 * n_keep;
    long long maxw = (long long)(CAP1 / 2);
    if (want > maxw) want = maxw;
    if (want < 2 * n_keep) want = 2 * n_keep;
    long long tgt = want / scale;
    if (tgt < 512) tgt = 512;
    unsigned target = (tgt > 0x7FFFFFFFLL) ? 0x7FFFFFFFu : (unsigned)tgt;

    unsigned S_after = ssum[t] - my;
    if (S_after < target && S_after + my >= target) {
        unsigned cum = S_after;
        for (int b = 4 * t + 3; b >= 4 * t; --b) {
            unsigned cc = c[b - 4 * t];
            if (cum + cc >= target) { g_lbin = (unsigned)b; break; }
            cum += cc;
        }
    }
    // no crossing -> lbin stays 0 (collect all positives; fallback covers overflow)
}

// ---------------------------------------------------------------------------
// Warp-aggregated candidate push. Must be called by all 32 lanes.
__device__ __forceinline__ void push1(bool pred, unsigned u, unsigned gidx) {
    unsigned mask = __ballot_sync(0xFFFFFFFFu, pred);
    if (!mask) return;
    int leader = __ffs(mask) - 1;
    int lane = threadIdx.x & 31;
    unsigned pos = 0;
    if (lane == leader) pos = atomicAdd(&g_cand_count, (unsigned)__popc(mask));
    pos = __shfl_sync(0xFFFFFFFFu, pos, leader);
    if (pred) {
        unsigned p = pos + __popc(mask & ((1u << lane) - 1u));
        if (p < CAP1)
            g_cand[p] = ((unsigned long long)u << 32) | (unsigned long long)gidx;
    }
}

// The one full pass: read x once, stream zeros to out, collect cands >= L.
__global__ void main_kernel(const float4* __restrict__ x4, float4* __restrict__ o4,
                            int n4, const float* __restrict__ x, float* __restrict__ o,
                            int n) {
    unsigned lbits = g_lbin << 19;
    int i = blockIdx.x * blockDim.x + threadIdx.x;
    float4 v = make_float4(0.f, 0.f, 0.f, 0.f);
    bool in = i < n4;
    if (in) v = __ldcs(&x4[i]);
    if (in) __stcs(&o4[i], make_float4(0.f, 0.f, 0.f, 0.f));
    unsigned base = (unsigned)i * 4u;

    unsigned ux = __float_as_uint(v.x);
    unsigned uy = __float_as_uint(v.y);
    unsigned uz = __float_as_uint(v.z);
    unsigned uw = __float_as_uint(v.w);
    // no early exit before ballots: all lanes participate
    push1(in && v.x > 0.f && ux >= lbits, ux, base + 0u);
    push1(in && v.y > 0.f && uy >= lbits, uy, base + 1u);
    push1(in && v.z > 0.f && uz >= lbits, uz, base + 2u);
    push1(in && v.w > 0.f && uw >= lbits, uw, base + 3u);

    int t0 = n4 * 4 + i;
    if (t0 < n) {
        float s = x[t0];
        o[t0] = 0.f;
        unsigned u = __float_as_uint(s);
        if (s > 0.f && u >= lbits) {
            unsigned p = atomicAdd(&g_cand_count, 1u);
            if (p < CAP1)
                g_cand[p] = ((unsigned long long)u << 32) | (unsigned long long)t0;
        }
    }
}

// ---------------------------------------------------------------------------
__global__ void candhist_kernel() {
    __shared__ unsigned int sh[HIST_BINS];
    for (int i = threadIdx.x; i < HIST_BINS; i += blockDim.x) sh[i] = 0;
    __syncthreads();
    unsigned m = min(g_cand_count, CAP1);
    unsigned stride = gridDim.x * blockDim.x;
    for (unsigned j = blockIdx.x * blockDim.x + threadIdx.x; j < m; j += stride) {
        unsigned u = (unsigned)(g_cand[j] >> 32);
        atomicAdd(&sh[u >> 19], 1u);
    }
    __syncthreads();
    for (int i = threadIdx.x; i < HIST_BINS; i += blockDim.x) {
        unsigned c = sh[i];
        if (c) atomicAdd(&g_hist[i], c);
    }
}

// ---------------------------------------------------------------------------
// mode 0: over candidate hist. mode 1 (fallback): over exact full hist.
__global__ void select_kernel(const int* __restrict__ kptr, long long num_samples,
                              int mode) {
    if (mode == 1 && !g_need_full) return;           // uniform
    __shared__ unsigned int ssum[1024];
    int t = threadIdx.x;
    long long n_keep = (long long)kptr[0] * num_samples;
    if (n_keep <= 0) {
        if (t == 0) { g_bucket = HIST_BINS; g_rem = 0; }
        return;                                       // uniform
    }
    if (mode == 0 && g_cand_count > CAP1) {           // overflow: exact fallback
        if (t == 0) g_need_full = 1;
        return;                                       // uniform
    }
    if (mode == 1 && t == 0) g_c2_count = 0;          // fresh in-bucket list for fb_write

    const unsigned* H = (mode == 0) ? g_hist : g_fhist;
    unsigned c[4];
#pragma unroll
    for (int q = 0; q < 4; q++) c[q] = H[4 * t + q];
    unsigned my = c[0] + c[1] + c[2] + c[3];
    ssum[t] = my;
    __syncthreads();
    for (int d = 1; d < 1024; d <<= 1) {
        unsigned v = ssum[t] + ((t + d < 1024) ? ssum[t + d] : 0u);
        __syncthreads();
        ssum[t] = v;
        __syncthreads();
    }
    unsigned total = ssum[0];
    unsigned S_after = ssum[t] - my;
    if ((long long)total < n_keep) {
        if (t == 0) {
            if (mode == 0) {
                if (g_lbin == 0u) { g_bucket = -1; g_rem = 0; }  // all positives kept
                else              { g_need_full = 1; }            // bound too high
            } else {
                g_bucket = -1; g_rem = 0;
            }
        }
        return;
    }
    if ((long long)S_after < n_keep && (long long)S_after + (long long)my >= n_keep) {
        unsigned cum = S_after;
        for (int b = 4 * t + 3; b >= 4 * t; --b) {
            unsigned cc = c[b - 4 * t];
            if ((long long)cum + (long long)cc >= n_keep) {
                g_bucket = b;
                g_rem = (unsigned)(n_keep - (long long)cum);
                break;
            }
            cum += cc;
        }
    }
}

// ---------------------------------------------------------------------------
// Normal path: emit >bucket candidates to out, gather ==bucket into g_cand2.
__global__ void scatter_kernel(float* __restrict__ out) {
    if (g_need_full) return;                          // uniform
    int bucket = g_bucket;
    if (bucket == HIST_BINS || bucket == -2) return;  // uniform
    unsigned m = min(g_cand_count, CAP1);
    unsigned stride = gridDim.x * blockDim.x;
    unsigned gtid = blockIdx.x * blockDim.x + threadIdx.x;
    unsigned trips = (m + stride - 1) / stride;
    int lane = threadIdx.x & 31;
    for (unsigned tIt = 0; tIt < trips; ++tIt) {
        unsigned j = gtid + tIt * stride;
        bool valid = j < m;
        unsigned long long cv = valid ? g_cand[j] : 0ull;
        unsigned u   = (unsigned)(cv >> 32);
        unsigned idx = (unsigned)cv;
        int bin = (int)(u >> 19);
        if (valid && (bucket == -1 || bin > bucket))
            out[idx] = __uint_as_float(u);
        bool mid = valid && bucket >= 0 && bin == bucket;
        unsigned mask = __ballot_sync(0xFFFFFFFFu, mid);
        if (mask) {
            int leader = __ffs(mask) - 1;
            unsigned pos = 0;
            if (lane == leader) pos = atomicAdd(&g_c2_count, (unsigned)__popc(mask));
            pos = __shfl_sync(0xFFFFFFFFu, pos, leader);
            if (mid) {
                unsigned p = pos + __popc(mask & ((1u << lane) - 1u));
                if (p < CAP2) g_cand2[p] = cv;
            }
        }
    }
}

// ---------------------------------------------------------------------------
// Fallback exact histogram (all positives). No-op unless need_full.
__global__ void fb_hist_kernel(const float4* __restrict__ x4, int n4,
                               const float* __restrict__ x, int n) {
    if (!g_need_full) return;
    __shared__ unsigned int sh[HIST_BINS];
    for (int i = threadIdx.x; i < HIST_BINS; i += blockDim.x) sh[i] = 0;
    __syncthreads();
    int stride = gridDim.x * blockDim.x;
    for (int i = blockIdx.x * blockDim.x + threadIdx.x; i < n4; i += stride) {
        float4 v = x4[i];
        if (v.x > 0.f) atomicAdd(&sh[__float_as_uint(v.x) >> 19], 1u);
        if (v.y > 0.f) atomicAdd(&sh[__float_as_uint(v.y) >> 19], 1u);
        if (v.z > 0.f) atomicAdd(&sh[__float_as_uint(v.z) >> 19], 1u);
        if (v.w > 0.f) atomicAdd(&sh[__float_as_uint(v.w) >> 19], 1u);
    }
    int t0 = n4 * 4 + blockIdx.x * blockDim.x + threadIdx.x;
    if (t0 < n) {
        float v = x[t0];
        if (v > 0.f) atomicAdd(&sh[__float_as_uint(v) >> 19], 1u);
    }
    __syncthreads();
    for (int i = threadIdx.x; i < HIST_BINS; i += blockDim.x) {
        unsigned c = sh[i];
        if (c) atomicAdd(&g_fhist[i], c);
    }
}

// Fallback exact write: classify every element. No-op unless need_full.
__global__ void fb_write_kernel(const float4* __restrict__ x4, float4* __restrict__ o4,
                                int n4, const float* __restrict__ x, float* __restrict__ o,
                                int n) {
    if (!g_need_full) return;
    int bucket = g_bucket;
    int stride = gridDim.x * blockDim.x;
    for (int i = blockIdx.x * blockDim.x + threadIdx.x; i < n4; i += stride) {
        float4 v = x4[i];
        float4 r;
        unsigned base = (unsigned)i * 4u;
        const float* vv = &v.x;
        float* rr = &r.x;
#pragma unroll
        for (int q = 0; q < 4; q++) {
            float s = vv[q];
            float outv = 0.f;
            if (s > 0.f) {
                unsigned u = __float_as_uint(s);
                int bin = (int)(u >> 19);
                if (bucket == -1 || bin > bucket) outv = s;
                else if (bin == bucket) {
                    unsigned p = atomicAdd(&g_c2_count, 1u);
                    if (p < CAP2)
                        g_cand2[p] = ((unsigned long long)u << 32) |
                                     (unsigned long long)(base + (unsigned)q);
                }
            }
            rr[q] = outv;
        }
        o4[i] = r;
    }
    int t0 = n4 * 4 + blockIdx.x * blockDim.x + threadIdx.x;
    if (t0 < n) {
        float s = x[t0];
        float outv = 0.f;
        if (s > 0.f) {
            unsigned u = __float_as_uint(s);
            int bin = (int)(u >> 19);
            if (bucket == -1 || bin > bucket) outv = s;
            else if (bin == bucket) {
                unsigned p = atomicAdd(&g_c2_count, 1u);
                if (p < CAP2)
                    g_cand2[p] = ((unsigned long long)u << 32) | (unsigned long long)t0;
            }
        }
        o[t0] = outv;
    }
}

// ---------------------------------------------------------------------------
__global__ void refine_kernel(float* __restrict__ out) {
    __shared__ unsigned int sh[8192];
    __shared__ unsigned int ssum[1024];
    __shared__ unsigned int eqidx[EQ_CAP];
    __shared__ unsigned int s_b1, s_r1, s_b2, s_r2, s_eqc;

    int bucket = g_bucket;
    if (bucket < 0 || bucket >= HIST_BINS) return;

    unsigned m = min(g_c2_count, CAP2);
    unsigned r = g_rem;
    int tid = threadIdx.x;

    // histogram bits [18:6]
    for (int i = tid; i < 8192; i += blockDim.x) sh[i] = 0;
    __syncthreads();
    for (unsigned i = tid; i < m; i += blockDim.x) {
        unsigned u = (unsigned)(g_cand2[i] >> 32);
        atomicAdd(&sh[(u >> 6) & 0x1FFFu], 1u);
    }
    __syncthreads();

    unsigned c8[8];
#pragma unroll
    for (int q = 0; q < 8; q++) c8[q] = sh[8 * tid + q];
    unsigned my = 0;
#pragma unroll
    for (int q = 0; q < 8; q++) my += c8[q];
    ssum[tid] = my;
    __syncthreads();
    for (int d = 1; d < 1024; d <<= 1) {
        unsigned v = ssum[tid] + ((tid + d < 1024) ? ssum[tid + d] : 0u);
        __syncthreads();
        ssum[tid] = v;
        __syncthreads();
    }
    unsigned S_after = ssum[tid] - my;
    if (S_after < r && S_after + my >= r) {
        unsigned cum = S_after;
        for (int b = 8 * tid + 7; b >= 8 * tid; --b) {
            unsigned cc = c8[b - 8 * tid];
            if (cum + cc >= r) { s_b1 = (unsigned)b; s_r1 = r - cum; break; }
            cum += cc;
        }
    }
    __syncthreads();
    unsigned b1 = s_b1, r1 = s_r1;

    // bits [5:0]
    for (int i = tid; i < 64; i += blockDim.x) sh[i] = 0;
    __syncthreads();
    for (unsigned i = tid; i < m; i += blockDim.x) {
        unsigned u = (unsigned)(g_cand2[i] >> 32);
        if (((u >> 6) & 0x1FFFu) == b1) atomicAdd(&sh[u & 0x3Fu], 1u);
    }
    __syncthreads();
    if (tid == 0) {
        unsigned cum = 0, rr = r1, b2 = 0;
        for (int i = 63; i >= 0; --i) {
            unsigned cc = sh[i];
            if (cum + cc >= rr) { b2 = (unsigned)i; rr -= cum; break; }
            cum += cc;
        }
        s_b2 = b2; s_r2 = rr; s_eqc = 0;
    }
    __syncthreads();
    unsigned b2 = s_b2, r2 = s_r2;
    unsigned T = ((unsigned)bucket << 19) | (b1 << 6) | b2;

    for (unsigned i = tid; i < m; i += blockDim.x) {
        unsigned long long cv = g_cand2[i];
        unsigned u   = (unsigned)(cv >> 32);
        unsigned idx = (unsigned)cv;
        if (u > T) {
            out[idx] = __uint_as_float(u);
        } else if (u == T) {
            unsigned p = atomicAdd(&s_eqc, 1u);
            if (p < EQ_CAP) eqidx[p] = idx;
        }
    }
    __syncthreads();

    unsigned ec = min(s_eqc, (unsigned)EQ_CAP);
    for (unsigned t = tid; t < ec; t += blockDim.x) {
        unsigned myi = eqidx[t];
        unsigned rank = 0;
        for (unsigned j = 0; j < ec; ++j)
            if (eqidx[j] < myi) rank++;
        if (rank < r2) out[myi] = __uint_as_float(T);
    }
}

// ---------------------------------------------------------------------------
extern "C" void kernel_launch(void* const* d_in, const int* in_sizes, int n_in,
                              void* d_out, int out_size) {
    const float* x  = (const float*)d_in[0];
    const int*   kp = (const int*)d_in[1];
    int n = in_sizes[0];
    long long num_samples = (long long)n / 16384;  // last dim = 16384
    int n4 = n / 4;

    init_kernel<<<(HIST_BINS + 255) / 256, 256>>>();
    sample_kernel<<<128, 256>>>((const float4*)x, n4);
    choose_kernel<<<1, 1024>>>(kp, num_samples, n, n4);

    int mb = (n4 + 255) / 256;
    if (mb < 1) mb = 1;
    main_kernel<<<mb, 256>>>((const float4*)x, (float4*)d_out, n4,
                             x, (float*)d_out, n);

    candhist_kernel<<<256, 256>>>();
    select_kernel<<<1, 1024>>>(kp, num_samples, 0);
    scatter_kernel<<<256, 256>>>((float*)d_out);

    // exact fallback chain (flag-gated no-ops in the common case)
    fb_hist_kernel<<<1184, 256>>>((const float4*)x, n4, x, n);
    select_kernel<<<1, 1024>>>(kp, num_samples, 1);
    fb_write_kernel<<<1184, 256>>>((const float4*)x, (float4*)d_out, n4,
                                   x, (float*)d_out, n);

    refine_kernel<<<1, 1024>>>((float*)d_out);
}

// round 5
// speedup vs baseline: 4.3604x; 4.3604x over previous
#include <cuda_runtime.h>

// ---------------------------------------------------------------------------
// BatchTopK: out = scatter(top_{k*rows}(relu(x))) over the FLATTENED array.
// R5: fused single full pass with PER-BLOCK SMEM candidate staging.
// R4 failed (571us) on single-address global atomic contention (~500K ATOMG
// on one counter, ~0.854cyc/op serialized) + ballot chains in the hot path.
// Now: rare predicated smem atomic per hit, ONE global atomic per block at
// flush, coalesced copy-out. Ballot-free hot loop (R1 write_kernel regime,
// 4.28 TB/s). Exact fallback chain unchanged.
// ---------------------------------------------------------------------------

#define HIST_BINS 4096
#define CAP1      (1u << 21)   // candidate list: 2M * 8B = 16MB
#define CAP2      (1u << 20)   // in-bucket list: 1M * 8B = 8MB
#define EQ_CAP    2048
#define SSTR4     128          // sample every 128th float4
#define BLK_ELEMS 1024         // elements per block in main pass (256 thr * 4)

__device__ unsigned int       g_shist[HIST_BINS];
__device__ unsigned int       g_hist[HIST_BINS];
__device__ unsigned int       g_fhist[HIST_BINS];
__device__ unsigned int       g_lbin;
__device__ int                g_bucket;       // -1 keep all positives; HIST_BINS keep none
__device__ unsigned int       g_rem;
__device__ int                g_need_full;
__device__ unsigned int       g_cand_count;
__device__ unsigned int       g_c2_count;
__device__ unsigned long long g_cand[CAP1];   // (bits<<32) | flat_index
__device__ unsigned long long g_cand2[CAP2];

// ---------------------------------------------------------------------------
__global__ void init_kernel() {
    int i = blockIdx.x * blockDim.x + threadIdx.x;
    if (i < HIST_BINS) { g_shist[i] = 0; g_hist[i] = 0; g_fhist[i] = 0; }
    if (i == 0) {
        g_cand_count = 0; g_c2_count = 0; g_bucket = -2; g_rem = 0;
        g_need_full = 0; g_lbin = 0;
    }
}

// ---------------------------------------------------------------------------
__global__ void sample_kernel(const float4* __restrict__ x4, int n4) {
    __shared__ unsigned int sh[HIST_BINS];
    for (int i = threadIdx.x; i < HIST_BINS; i += blockDim.x) sh[i] = 0;
    __syncthreads();
    int ns = n4 / SSTR4;
    int stride = gridDim.x * blockDim.x;
    for (int j = blockIdx.x * blockDim.x + threadIdx.x; j < ns; j += stride) {
        float4 v = x4[(size_t)j * SSTR4];
        if (v.x > 0.f) atomicAdd(&sh[__float_as_uint(v.x) >> 19], 1u);
        if (v.y > 0.f) atomicAdd(&sh[__float_as_uint(v.y) >> 19], 1u);
        if (v.z > 0.f) atomicAdd(&sh[__float_as_uint(v.z) >> 19], 1u);
        if (v.w > 0.f) atomicAdd(&sh[__float_as_uint(v.w) >> 19], 1u);
    }
    __syncthreads();
    for (int i = threadIdx.x; i < HIST_BINS; i += blockDim.x) {
        unsigned c = sh[i];
        if (c) atomicAdd(&g_shist[i], c);
    }
}

// ---------------------------------------------------------------------------
// lbin = largest bin whose sampled suffix count covers ~4x n_keep.
__global__ void choose_kernel(const int* __restrict__ kptr, long long num_samples,
                              int n, int n4) {
    __shared__ unsigned int ssum[1024];
    int t = threadIdx.x;
    unsigned c[4];
#pragma unroll
    for (int q = 0; q < 4; q++) c[q] = g_shist[4 * t + q];
    unsigned my = c[0] + c[1] + c[2] + c[3];
    ssum[t] = my;
    __syncthreads();
    for (int d = 1; d < 1024; d <<= 1) {
        unsigned v = ssum[t] + ((t + d < 1024) ? ssum[t + d] : 0u);
        __syncthreads();
        ssum[t] = v;
        __syncthreads();
    }
    long long n_keep = (long long)kptr[0] * num_samples;
    long long sampled = (long long)(n4 / SSTR4) * 4;
    if (sampled < 1) sampled = 1;
    long long scale = ((long long)n + sampled - 1) / sampled;
    if (scale < 1) scale = 1;
    long long want = 4 * n_keep;
    long long maxw = (long long)(CAP1 / 2);
    if (want > maxw) want = maxw;
    if (want < 2 * n_keep) want = 2 * n_keep;
    long long tgt = want / scale;
    if (tgt < 512) tgt = 512;
    unsigned target = (tgt > 0x7FFFFFFFLL) ? 0x7FFFFFFFu : (unsigned)tgt;

    unsigned S_after = ssum[t] - my;
    if (S_after < target && S_after + my >= target) {
        unsigned cum = S_after;
        for (int b = 4 * t + 3; b >= 4 * t; --b) {
            unsigned cc = c[b - 4 * t];
            if (cum + cc >= target) { g_lbin = (unsigned)b; break; }
            cum += cc;
        }
    }
    // no crossing -> lbin stays 0 (collect all positives; fallback covers overflow)
}

// ---------------------------------------------------------------------------
// Fused full pass: read x once, stream zeros to out, stage candidates >= L in
// SMEM (ballot-free; buffer == block element count so it cannot overflow),
// flush once per block.
__global__ void main_kernel(const float4* __restrict__ x4, float4* __restrict__ o4,
                            int n4, const float* __restrict__ x, float* __restrict__ o,
                            int n) {
    __shared__ unsigned long long sbuf[BLK_ELEMS];
    __shared__ unsigned int s_cnt;
    __shared__ unsigned int s_base;
    if (threadIdx.x == 0) s_cnt = 0;
    __syncthreads();

    unsigned lbits = g_lbin << 19;
    int i = blockIdx.x * blockDim.x + threadIdx.x;
    if (i < n4) {
        float4 v = __ldcs(&x4[i]);
        __stcs(&o4[i], make_float4(0.f, 0.f, 0.f, 0.f));
        unsigned base = (unsigned)i * 4u;
        unsigned u;
        u = __float_as_uint(v.x);
        if (v.x > 0.f && u >= lbits) {
            unsigned p = atomicAdd(&s_cnt, 1u);
            sbuf[p] = ((unsigned long long)u << 32) | (unsigned long long)(base + 0u);
        }
        u = __float_as_uint(v.y);
        if (v.y > 0.f && u >= lbits) {
            unsigned p = atomicAdd(&s_cnt, 1u);
            sbuf[p] = ((unsigned long long)u << 32) | (unsigned long long)(base + 1u);
        }
        u = __float_as_uint(v.z);
        if (v.z > 0.f && u >= lbits) {
            unsigned p = atomicAdd(&s_cnt, 1u);
            sbuf[p] = ((unsigned long long)u << 32) | (unsigned long long)(base + 2u);
        }
        u = __float_as_uint(v.w);
        if (v.w > 0.f && u >= lbits) {
            unsigned p = atomicAdd(&s_cnt, 1u);
            sbuf[p] = ((unsigned long long)u << 32) | (unsigned long long)(base + 3u);
        }
    }
    int t0 = n4 * 4 + i;
    if (t0 < n) {
        float s = x[t0];
        o[t0] = 0.f;
        unsigned u = __float_as_uint(s);
        if (s > 0.f && u >= lbits) {
            unsigned p = atomicAdd(&s_cnt, 1u);
            sbuf[p] = ((unsigned long long)u << 32) | (unsigned long long)t0;
        }
    }
    __syncthreads();

    unsigned cnt = s_cnt;
    if (cnt == 0) return;
    if (threadIdx.x == 0) {
        s_base = atomicAdd(&g_cand_count, cnt);
        if (s_base + cnt > CAP1) g_need_full = 1;   // capacity edge -> exact path
    }
    __syncthreads();
    unsigned gb = s_base;
    for (unsigned j = threadIdx.x; j < cnt; j += blockDim.x) {
        unsigned p = gb + j;
        if (p < CAP1) g_cand[p] = sbuf[j];
    }
}

// ---------------------------------------------------------------------------
__global__ void candhist_kernel() {
    if (g_need_full) return;                      // uniform
    __shared__ unsigned int sh[HIST_BINS];
    for (int i = threadIdx.x; i < HIST_BINS; i += blockDim.x) sh[i] = 0;
    __syncthreads();
    unsigned m = min(g_cand_count, CAP1);
    unsigned stride = gridDim.x * blockDim.x;
    for (unsigned j = blockIdx.x * blockDim.x + threadIdx.x; j < m; j += stride) {
        unsigned u = (unsigned)(g_cand[j] >> 32);
        atomicAdd(&sh[u >> 19], 1u);
    }
    __syncthreads();
    for (int i = threadIdx.x; i < HIST_BINS; i += blockDim.x) {
        unsigned c = sh[i];
        if (c) atomicAdd(&g_hist[i], c);
    }
}

// ---------------------------------------------------------------------------
// mode 0: over candidate hist. mode 1 (fallback): over exact full hist.
__global__ void select_kernel(const int* __restrict__ kptr, long long num_samples,
                              int mode) {
    if (mode == 0 && g_need_full) return;        // uniform (capacity overflow)
    if (mode == 1 && !g_need_full) return;       // uniform
    __shared__ unsigned int ssum[1024];
    int t = threadIdx.x;
    long long n_keep = (long long)kptr[0] * num_samples;
    if (n_keep <= 0) {
        if (t == 0) { g_bucket = HIST_BINS; g_rem = 0; }
        return;                                   // uniform
    }
    if (mode == 1 && t == 0) g_c2_count = 0;      // fresh list for fb_write

    const unsigned* H = (mode == 0) ? g_hist : g_fhist;
    unsigned c[4];
#pragma unroll
    for (int q = 0; q < 4; q++) c[q] = H[4 * t + q];
    unsigned my = c[0] + c[1] + c[2] + c[3];
    ssum[t] = my;
    __syncthreads();
    for (int d = 1; d < 1024; d <<= 1) {
        unsigned v = ssum[t] + ((t + d < 1024) ? ssum[t + d] : 0u);
        __syncthreads();
        ssum[t] = v;
        __syncthreads();
    }
    unsigned total = ssum[0];
    unsigned S_after = ssum[t] - my;
    if ((long long)total < n_keep) {
        if (t == 0) {
            if (mode == 0) {
                if (g_lbin == 0u) { g_bucket = -1; g_rem = 0; }  // all positives kept
                else              { g_need_full = 1; }            // bound too high
            } else {
                g_bucket = -1; g_rem = 0;
            }
        }
        return;
    }
    if ((long long)S_after < n_keep && (long long)S_after + (long long)my >= n_keep) {
        unsigned cum = S_after;
        for (int b = 4 * t + 3; b >= 4 * t; --b) {
            unsigned cc = c[b - 4 * t];
            if ((long long)cum + (long long)cc >= n_keep) {
                g_bucket = b;
                g_rem = (unsigned)(n_keep - (long long)cum);
                break;
            }
            cum += cc;
        }
    }
}

// ---------------------------------------------------------------------------
// Normal path: emit >bucket candidates to out, gather ==bucket into g_cand2.
// List is small (~512K) so warp-aggregated push cost is negligible here.
__global__ void scatter_kernel(float* __restrict__ out) {
    if (g_need_full) return;                          // uniform
    int bucket = g_bucket;
    if (bucket == HIST_BINS || bucket == -2) return;  // uniform
    unsigned m = min(g_cand_count, CAP1);
    unsigned stride = gridDim.x * blockDim.x;
    unsigned gtid = blockIdx.x * blockDim.x + threadIdx.x;
    unsigned trips = (m + stride - 1) / stride;
    int lane = threadIdx.x & 31;
    for (unsigned tIt = 0; tIt < trips; ++tIt) {
        unsigned j = gtid + tIt * stride;
        bool valid = j < m;
        unsigned long long cv = valid ? g_cand[j] : 0ull;
        unsigned u   = (unsigned)(cv >> 32);
        unsigned idx = (unsigned)cv;
        int bin = (int)(u >> 19);
        if (valid && (bucket == -1 || bin > bucket))
            out[idx] = __uint_as_float(u);
        bool mid = valid && bucket >= 0 && bin == bucket;
        unsigned mask = __ballot_sync(0xFFFFFFFFu, mid);
        if (mask) {
            int leader = __ffs(mask) - 1;
            unsigned pos = 0;
            if (lane == leader) pos = atomicAdd(&g_c2_count, (unsigned)__popc(mask));
            pos = __shfl_sync(0xFFFFFFFFu, pos, leader);
            if (mid) {
                unsigned p = pos + __popc(mask & ((1u << lane) - 1u));
                if (p < CAP2) g_cand2[p] = cv;
            }
        }
    }
}

// ---------------------------------------------------------------------------
// Fallback exact histogram (all positives). No-op unless need_full.
__global__ void fb_hist_kernel(const float4* __restrict__ x4, int n4,
                               const float* __restrict__ x, int n) {
    if (!g_need_full) return;
    __shared__ unsigned int sh[HIST_BINS];
    for (int i = threadIdx.x; i < HIST_BINS; i += blockDim.x) sh[i] = 0;
    __syncthreads();
    int stride = gridDim.x * blockDim.x;
    for (int i = blockIdx.x * blockDim.x + threadIdx.x; i < n4; i += stride) {
        float4 v = x4[i];
        if (v.x > 0.f) atomicAdd(&sh[__float_as_uint(v.x) >> 19], 1u);
        if (v.y > 0.f) atomicAdd(&sh[__float_as_uint(v.y) >> 19], 1u);
        if (v.z > 0.f) atomicAdd(&sh[__float_as_uint(v.z) >> 19], 1u);
        if (v.w > 0.f) atomicAdd(&sh[__float_as_uint(v.w) >> 19], 1u);
    }
    int t0 = n4 * 4 + blockIdx.x * blockDim.x + threadIdx.x;
    if (t0 < n) {
        float v = x[t0];
        if (v > 0.f) atomicAdd(&sh[__float_as_uint(v) >> 19], 1u);
    }
    __syncthreads();
    for (int i = threadIdx.x; i < HIST_BINS; i += blockDim.x) {
        unsigned c = sh[i];
        if (c) atomicAdd(&g_fhist[i], c);
    }
}

// Fallback exact write. No-op unless need_full.
__global__ void fb_write_kernel(const float4* __restrict__ x4, float4* __restrict__ o4,
                                int n4, const float* __restrict__ x, float* __restrict__ o,
                                int n) {
    if (!g_need_full) return;
    int bucket = g_bucket;
    int stride = gridDim.x * blockDim.x;
    for (int i = blockIdx.x * blockDim.x + threadIdx.x; i < n4; i += stride) {
        float4 v = x4[i];
        float4 r;
        unsigned base = (unsigned)i * 4u;
        const float* vv = &v.x;
        float* rr = &r.x;
#pragma unroll
        for (int q = 0; q < 4; q++) {
            float s = vv[q];
            float outv = 0.f;
            if (s > 0.f) {
                unsigned u = __float_as_uint(s);
                int bin = (int)(u >> 19);
                if (bucket == -1 || bin > bucket) outv = s;
                else if (bin == bucket) {
                    unsigned p = atomicAdd(&g_c2_count, 1u);
                    if (p < CAP2)
                        g_cand2[p] = ((unsigned long long)u << 32) |
                                     (unsigned long long)(base + (unsigned)q);
                }
            }
            rr[q] = outv;
        }
        o4[i] = r;
    }
    int t0 = n4 * 4 + blockIdx.x * blockDim.x + threadIdx.x;
    if (t0 < n) {
        float s = x[t0];
        float outv = 0.f;
        if (s > 0.f) {
            unsigned u = __float_as_uint(s);
            int bin = (int)(u >> 19);
            if (bucket == -1 || bin > bucket) outv = s;
            else if (bin == bucket) {
                unsigned p = atomicAdd(&g_c2_count, 1u);
                if (p < CAP2)
                    g_cand2[p] = ((unsigned long long)u << 32) | (unsigned long long)t0;
            }
        }
        o[t0] = outv;
    }
}

// ---------------------------------------------------------------------------
__global__ void refine_kernel(float* __restrict__ out) {
    __shared__ unsigned int sh[8192];
    __shared__ unsigned int ssum[1024];
    __shared__ unsigned int eqidx[EQ_CAP];
    __shared__ unsigned int s_b1, s_r1, s_b2, s_r2, s_eqc;

    int bucket = g_bucket;
    if (bucket < 0 || bucket >= HIST_BINS) return;

    unsigned m = min(g_c2_count, CAP2);
    unsigned r = g_rem;
    int tid = threadIdx.x;

    for (int i = tid; i < 8192; i += blockDim.x) sh[i] = 0;
    __syncthreads();
    for (unsigned i = tid; i < m; i += blockDim.x) {
        unsigned u = (unsigned)(g_cand2[i] >> 32);
        atomicAdd(&sh[(u >> 6) & 0x1FFFu], 1u);
    }
    __syncthreads();

    unsigned c8[8];
#pragma unroll
    for (int q = 0; q < 8; q++) c8[q] = sh[8 * tid + q];
    unsigned my = 0;
#pragma unroll
    for (int q = 0; q < 8; q++) my += c8[q];
    ssum[tid] = my;
    __syncthreads();
    for (int d = 1; d < 1024; d <<= 1) {
        unsigned v = ssum[tid] + ((tid + d < 1024) ? ssum[tid + d] : 0u);
        __syncthreads();
        ssum[tid] = v;
        __syncthreads();
    }
    unsigned S_after = ssum[tid] - my;
    if (S_after < r && S_after + my >= r) {
        unsigned cum = S_after;
        for (int b = 8 * tid + 7; b >= 8 * tid; --b) {
            unsigned cc = c8[b - 8 * tid];
            if (cum + cc >= r) { s_b1 = (unsigned)b; s_r1 = r - cum; break; }
            cum += cc;
        }
    }
    __syncthreads();
    unsigned b1 = s_b1, r1 = s_r1;

    for (int i = tid; i < 64; i += blockDim.x) sh[i] = 0;
    __syncthreads();
    for (unsigned i = tid; i < m; i += blockDim.x) {
        unsigned u = (unsigned)(g_cand2[i] >> 32);
        if (((u >> 6) & 0x1FFFu) == b1) atomicAdd(&sh[u & 0x3Fu], 1u);
    }
    __syncthreads();
    if (tid == 0) {
        unsigned cum = 0, rr = r1, b2 = 0;
        for (int i = 63; i >= 0; --i) {
            unsigned cc = sh[i];
            if (cum + cc >= rr) { b2 = (unsigned)i; rr -= cum; break; }
            cum += cc;
        }
        s_b2 = b2; s_r2 = rr; s_eqc = 0;
    }
    __syncthreads();
    unsigned b2 = s_b2, r2 = s_r2;
    unsigned T = ((unsigned)bucket << 19) | (b1 << 6) | b2;

    for (unsigned i = tid; i < m; i += blockDim.x) {
        unsigned long long cv = g_cand2[i];
        unsigned u   = (unsigned)(cv >> 32);
        unsigned idx = (unsigned)cv;
        if (u > T) {
            out[idx] = __uint_as_float(u);
        } else if (u == T) {
            unsigned p = atomicAdd(&s_eqc, 1u);
            if (p < EQ_CAP) eqidx[p] = idx;
        }
    }
    __syncthreads();

    unsigned ec = min(s_eqc, (unsigned)EQ_CAP);
    for (unsigned t = tid; t < ec; t += blockDim.x) {
        unsigned myi = eqidx[t];
        unsigned rank = 0;
        for (unsigned j = 0; j < ec; ++j)
            if (eqidx[j] < myi) rank++;
        if (rank < r2) out[myi] = __uint_as_float(T);
    }
}

// ---------------------------------------------------------------------------
extern "C" void kernel_launch(void* const* d_in, const int* in_sizes, int n_in,
                              void* d_out, int out_size) {
    const float* x  = (const float*)d_in[0];
    const int*   kp = (const int*)d_in[1];
    int n = in_sizes[0];
    long long num_samples = (long long)n / 16384;  // last dim = 16384
    int n4 = n / 4;

    init_kernel<<<(HIST_BINS + 255) / 256, 256>>>();
    sample_kernel<<<128, 256>>>((const float4*)x, n4);
    choose_kernel<<<1, 1024>>>(kp, num_samples, n, n4);

    int mb = (n4 + 255) / 256;
    if (mb < 1) mb = 1;
    main_kernel<<<mb, 256>>>((const float4*)x, (float4*)d_out, n4,
                             x, (float*)d_out, n);

    candhist_kernel<<<256, 256>>>();
    select_kernel<<<1, 1024>>>(kp, num_samples, 0);
    scatter_kernel<<<256, 256>>>((float*)d_out);

    // exact fallback chain (flag-gated no-ops in the common case)
    fb_hist_kernel<<<1184, 256>>>((const float4*)x, n4, x, n);
    select_kernel<<<1, 1024>>>(kp, num_samples, 1);
    fb_write_kernel<<<1184, 256>>>((const float4*)x, (float4*)d_out, n4,
                                   x, (float*)d_out, n);

    refine_kernel<<<1, 1024>>>((float*)d_out);
}

// round 6
// speedup vs baseline: 4.9833x; 1.1429x over previous
#include <cuda_runtime.h>

// ---------------------------------------------------------------------------
// BatchTopK: out = scatter(top_{k*rows}(relu(x))) over the FLATTENED array.
// R6: 5-launch pipeline with last-block-done fusion.
//   K1 sample  (+choose in last block)          - pick lower bound L
//   K2 main    (fused: read x once, zero out, stage candidates >=L in SMEM)
//   K3 candhist(+select in last block)          - 4096-bin hist + bucket
//   K4 scatter (+refine in last block)          - emit >bucket, exact 32-bit
//   K5 fallback (single block; exact slow path, flag-gated; also cleanup)
// All state self-restoring per replay (no init kernel).
// ---------------------------------------------------------------------------

#define HIST_BINS 4096
#define CAP1      (1u << 21)   // candidate list: 2M * 8B = 16MB
#define CAP2      (1u << 20)   // in-bucket list: 1M * 8B = 8MB
#define EQ_CAP    2048
#define SSTR4     256          // sample every 256th float4

#define SAMPLE_BLOCKS 128
#define CH_BLOCKS     256
#define SC_BLOCKS     128

__device__ unsigned int       g_shist[HIST_BINS];
__device__ unsigned int       g_hist[HIST_BINS];
__device__ unsigned int       g_lbin;
__device__ int                g_bucket;       // -1 keep all positives; HIST_BINS keep none
__device__ unsigned int       g_rem;
__device__ int                g_need_full;
__device__ unsigned int       g_cand_count;
__device__ unsigned int       g_c2_count;
__device__ unsigned int       g_done1, g_done2, g_done3;
__device__ unsigned long long g_cand[CAP1];   // (bits<<32) | flat_index
__device__ unsigned long long g_cand2[CAP2];

// ---------------------------------------------------------------------------
// Shared refine body: exact 32-bit threshold over g_cand2. blockDim.x == 1024.
__device__ void refine_body(float* __restrict__ out, int bucket, unsigned r,
                            unsigned m, unsigned* sh /*8192*/,
                            unsigned* ssum /*1024*/, unsigned* eqidx /*EQ_CAP*/,
                            unsigned* misc /*>=8*/) {
    int tid = threadIdx.x;

    // histogram of bits [18:6]
    for (int i = tid; i < 8192; i += 1024) sh[i] = 0;
    __syncthreads();
    for (unsigned i = tid; i < m; i += 1024) {
        unsigned u = (unsigned)(__ldcg(&g_cand2[i]) >> 32);
        atomicAdd(&sh[(u >> 6) & 0x1FFFu], 1u);
    }
    __syncthreads();

    unsigned c8[8];
#pragma unroll
    for (int q = 0; q < 8; q++) c8[q] = sh[8 * tid + q];
    unsigned my = 0;
#pragma unroll
    for (int q = 0; q < 8; q++) my += c8[q];
    ssum[tid] = my;
    __syncthreads();
    for (int d = 1; d < 1024; d <<= 1) {
        unsigned v = ssum[tid] + ((tid + d < 1024) ? ssum[tid + d] : 0u);
        __syncthreads();
        ssum[tid] = v;
        __syncthreads();
    }
    unsigned S_after = ssum[tid] - my;
    if (S_after < r && S_after + my >= r) {
        unsigned cum = S_after;
        for (int b = 8 * tid + 7; b >= 8 * tid; --b) {
            unsigned cc = c8[b - 8 * tid];
            if (cum + cc >= r) { misc[0] = (unsigned)b; misc[1] = r - cum; break; }
            cum += cc;
        }
    }
    __syncthreads();
    unsigned b1 = misc[0], r1 = misc[1];

    // bits [5:0]
    for (int i = tid; i < 64; i += 1024) sh[i] = 0;
    __syncthreads();
    for (unsigned i = tid; i < m; i += 1024) {
        unsigned u = (unsigned)(__ldcg(&g_cand2[i]) >> 32);
        if (((u >> 6) & 0x1FFFu) == b1) atomicAdd(&sh[u & 0x3Fu], 1u);
    }
    __syncthreads();
    if (tid == 0) {
        unsigned cum = 0, rr = r1, b2 = 0;
        for (int i = 63; i >= 0; --i) {
            unsigned cc = sh[i];
            if (cum + cc >= rr) { b2 = (unsigned)i; rr -= cum; break; }
            cum += cc;
        }
        misc[2] = b2; misc[3] = rr; misc[4] = 0;
    }
    __syncthreads();
    unsigned b2 = misc[2], r2 = misc[3];
    unsigned T = ((unsigned)bucket << 19) | (b1 << 6) | b2;

    for (unsigned i = tid; i < m; i += 1024) {
        unsigned long long cv = __ldcg(&g_cand2[i]);
        unsigned u   = (unsigned)(cv >> 32);
        unsigned idx = (unsigned)cv;
        if (u > T) {
            out[idx] = __uint_as_float(u);
        } else if (u == T) {
            unsigned p = atomicAdd(&misc[4], 1u);
            if (p < EQ_CAP) eqidx[p] = idx;
        }
    }
    __syncthreads();

    unsigned ec = min(misc[4], (unsigned)EQ_CAP);
    for (unsigned t = tid; t < ec; t += 1024) {
        unsigned myi = eqidx[t];
        unsigned rank = 0;
        for (unsigned j = 0; j < ec; ++j)
            if (eqidx[j] < myi) rank++;
        if (rank < r2) out[myi] = __uint_as_float(T);
    }
}

// ---------------------------------------------------------------------------
// K1: sampled histogram; last block runs choose (picks g_lbin), zeroes g_shist.
__global__ void sample_kernel(const float4* __restrict__ x4, int n4, int n,
                              const int* __restrict__ kptr, long long num_samples) {
    __shared__ unsigned int sh[HIST_BINS];
    __shared__ unsigned int ssum[256];
    __shared__ unsigned int s_lbin;
    __shared__ int s_last;
    int t = threadIdx.x;
    for (int i = t; i < HIST_BINS; i += blockDim.x) sh[i] = 0;
    __syncthreads();
    int ns = n4 / SSTR4;
    int stride = gridDim.x * blockDim.x;
    for (int j = blockIdx.x * blockDim.x + t; j < ns; j += stride) {
        float4 v = x4[(size_t)j * SSTR4];
        if (v.x > 0.f) atomicAdd(&sh[__float_as_uint(v.x) >> 19], 1u);
        if (v.y > 0.f) atomicAdd(&sh[__float_as_uint(v.y) >> 19], 1u);
        if (v.z > 0.f) atomicAdd(&sh[__float_as_uint(v.z) >> 19], 1u);
        if (v.w > 0.f) atomicAdd(&sh[__float_as_uint(v.w) >> 19], 1u);
    }
    __syncthreads();
    for (int i = t; i < HIST_BINS; i += blockDim.x) {
        unsigned c = sh[i];
        if (c) atomicAdd(&g_shist[i], c);
    }
    __threadfence();
    if (t == 0) {
        unsigned d = atomicAdd(&g_done1, 1u);
        s_last = (d == gridDim.x - 1u);
    }
    __syncthreads();
    if (!s_last) return;

    // ---- choose (256 threads, 16 bins each) ----
    if (t == 0) s_lbin = 0u;
    unsigned c16[16];
#pragma unroll
    for (int q = 0; q < 16; q++) c16[q] = __ldcg(&g_shist[16 * t + q]);
    unsigned my = 0;
#pragma unroll
    for (int q = 0; q < 16; q++) my += c16[q];
    ssum[t] = my;
    __syncthreads();
    for (int d = 1; d < 256; d <<= 1) {
        unsigned v = ssum[t] + ((t + d < 256) ? ssum[t + d] : 0u);
        __syncthreads();
        ssum[t] = v;
        __syncthreads();
    }
    long long n_keep = (long long)kptr[0] * num_samples;
    long long sampled = (long long)ns * 4;
    if (sampled < 1) sampled = 1;
    long long scale = ((long long)n + sampled - 1) / sampled;
    if (scale < 1) scale = 1;
    long long want = 4 * n_keep;
    long long maxw = (long long)(CAP1 / 2);
    if (want > maxw) want = maxw;
    if (want < 2 * n_keep) want = 2 * n_keep;
    long long tgt = want / scale;
    if (tgt < 512) tgt = 512;
    unsigned target = (tgt > 0x7FFFFFFFLL) ? 0x7FFFFFFFu : (unsigned)tgt;

    unsigned S_after = ssum[t] - my;
    if (S_after < target && S_after + my >= target) {
        unsigned cum = S_after;
        for (int b = 16 * t + 15; b >= 16 * t; --b) {
            unsigned cc = c16[b - 16 * t];
            if (cum + cc >= target) { s_lbin = (unsigned)b; break; }
            cum += cc;
        }
    }
    __syncthreads();
    if (t == 0) { g_lbin = s_lbin; g_done1 = 0u; }
    // zero g_shist for next replay
    for (int i = t; i < HIST_BINS; i += blockDim.x) g_shist[i] = 0u;
}

// ---------------------------------------------------------------------------
// K2: fused full pass. 2 float4 per thread (MLP), SMEM candidate staging.
__global__ void main_kernel(const float4* __restrict__ x4, float4* __restrict__ o4,
                            int n4, const float* __restrict__ x, float* __restrict__ o,
                            int n, int total_threads) {
    __shared__ unsigned long long sbuf[2176];
    __shared__ unsigned int s_cnt;
    __shared__ unsigned int s_base;
    if (threadIdx.x == 0) s_cnt = 0;
    __syncthreads();

    unsigned lbits = g_lbin << 19;
    int gtid = blockIdx.x * blockDim.x + threadIdx.x;
    int i1 = gtid, i2 = gtid + total_threads;
    bool b1 = i1 < n4, b2 = i2 < n4;
    float4 v1 = make_float4(0.f,0.f,0.f,0.f), v2 = v1;
    if (b1) v1 = __ldcs(&x4[i1]);
    if (b2) v2 = __ldcs(&x4[i2]);
    float4 z = make_float4(0.f, 0.f, 0.f, 0.f);
    if (b1) __stcs(&o4[i1], z);
    if (b2) __stcs(&o4[i2], z);

#define PUSH(val, gi)                                                     \
    { unsigned _u = __float_as_uint(val);                                 \
      if ((val) > 0.f && _u >= lbits) {                                   \
          unsigned _p = atomicAdd(&s_cnt, 1u);                            \
          sbuf[_p] = ((unsigned long long)_u << 32) |                     \
                     (unsigned long long)(gi); } }
    if (b1) {
        unsigned base = (unsigned)i1 * 4u;
        PUSH(v1.x, base + 0u); PUSH(v1.y, base + 1u);
        PUSH(v1.z, base + 2u); PUSH(v1.w, base + 3u);
    }
    if (b2) {
        unsigned base = (unsigned)i2 * 4u;
        PUSH(v2.x, base + 0u); PUSH(v2.y, base + 1u);
        PUSH(v2.z, base + 2u); PUSH(v2.w, base + 3u);
    }
    int t0 = n4 * 4 + gtid;
    if (t0 < n) {
        float s = x[t0];
        o[t0] = 0.f;
        PUSH(s, (unsigned)t0);
    }
#undef PUSH
    __syncthreads();

    unsigned cnt = s_cnt;
    if (cnt == 0) return;
    if (threadIdx.x == 0) {
        s_base = atomicAdd(&g_cand_count, cnt);
        if (s_base + cnt > CAP1) g_need_full = 1;
    }
    __syncthreads();
    unsigned gb = s_base;
    for (unsigned j = threadIdx.x; j < cnt; j += blockDim.x) {
        unsigned p = gb + j;
        if (p < CAP1) g_cand[p] = sbuf[j];
    }
}

// ---------------------------------------------------------------------------
// K3: 4096-bin hist over candidates; last block runs select, zeroes g_hist.
__global__ void candhist_kernel(const int* __restrict__ kptr, long long num_samples) {
    __shared__ unsigned int sh[HIST_BINS];
    __shared__ unsigned int ssum[256];
    __shared__ int s_last;
    int t = threadIdx.x;
    int nf = __ldcg(&g_need_full);
    if (!nf) {
        for (int i = t; i < HIST_BINS; i += blockDim.x) sh[i] = 0;
        __syncthreads();
        unsigned m = min(g_cand_count, CAP1);
        unsigned stride = gridDim.x * blockDim.x;
        for (unsigned j = blockIdx.x * blockDim.x + t; j < m; j += stride) {
            unsigned u = (unsigned)(g_cand[j] >> 32);
            atomicAdd(&sh[u >> 19], 1u);
        }
        __syncthreads();
        for (int i = t; i < HIST_BINS; i += blockDim.x) {
            unsigned c = sh[i];
            if (c) atomicAdd(&g_hist[i], c);
        }
    }
    __threadfence();
    if (t == 0) {
        unsigned d = atomicAdd(&g_done2, 1u);
        s_last = (d == gridDim.x - 1u);
    }
    __syncthreads();
    if (!s_last) return;

    // ---- select (256 threads, 16 bins each) ----
    long long n_keep = (long long)kptr[0] * num_samples;
    if (!nf) {
        if (n_keep <= 0) {
            if (t == 0) { g_bucket = HIST_BINS; g_rem = 0; }
        } else {
            unsigned c16[16];
#pragma unroll
            for (int q = 0; q < 16; q++) c16[q] = __ldcg(&g_hist[16 * t + q]);
            unsigned my = 0;
#pragma unroll
            for (int q = 0; q < 16; q++) my += c16[q];
            ssum[t] = my;
            __syncthreads();
            for (int d = 1; d < 256; d <<= 1) {
                unsigned v = ssum[t] + ((t + d < 256) ? ssum[t + d] : 0u);
                __syncthreads();
                ssum[t] = v;
                __syncthreads();
            }
            unsigned total = ssum[0];
            unsigned S_after = ssum[t] - my;
            if ((long long)total < n_keep) {
                if (t == 0) {
                    if (g_lbin == 0u) { g_bucket = -1; g_rem = 0; }
                    else              { g_need_full = 1; }
                }
            } else if ((long long)S_after < n_keep &&
                       (long long)S_after + (long long)my >= n_keep) {
                unsigned cum = S_after;
                for (int b = 16 * t + 15; b >= 16 * t; --b) {
                    unsigned cc = c16[b - 16 * t];
                    if ((long long)cum + (long long)cc >= n_keep) {
                        g_bucket = b;
                        g_rem = (unsigned)(n_keep - (long long)cum);
                        break;
                    }
                    cum += cc;
                }
            }
            __syncthreads();
        }
    }
    // zero g_hist for next replay; reset done
    for (int i = t; i < HIST_BINS; i += blockDim.x) g_hist[i] = 0u;
    if (t == 0) g_done2 = 0u;
}

// ---------------------------------------------------------------------------
// K4: emit >bucket to out, collect ==bucket into g_cand2; last block refines.
__global__ void scatter_kernel(float* __restrict__ out) {
    __shared__ unsigned int sh[8192];
    __shared__ unsigned int ssum[1024];
    __shared__ unsigned int eqidx[EQ_CAP];
    __shared__ unsigned int misc[8];
    __shared__ int s_last;
    int t = threadIdx.x;
    int nf = __ldcg(&g_need_full);
    int bucket = g_bucket;
    bool work = (!nf) && bucket != HIST_BINS;
    if (work) {
        unsigned m = min(g_cand_count, CAP1);
        unsigned stride = gridDim.x * blockDim.x;
        unsigned gtid = blockIdx.x * blockDim.x + t;
        unsigned trips = (m + stride - 1) / stride;
        int lane = t & 31;
        for (unsigned tIt = 0; tIt < trips; ++tIt) {
            unsigned j = gtid + tIt * stride;
            bool valid = j < m;
            unsigned long long cv = valid ? g_cand[j] : 0ull;
            unsigned u   = (unsigned)(cv >> 32);
            unsigned idx = (unsigned)cv;
            int bin = (int)(u >> 19);
            if (valid && (bucket == -1 || bin > bucket))
                out[idx] = __uint_as_float(u);
            bool mid = valid && bucket >= 0 && bin == bucket;
            unsigned mask = __ballot_sync(0xFFFFFFFFu, mid);
            if (mask) {
                int leader = __ffs(mask) - 1;
                unsigned pos = 0;
                if (lane == leader)
                    pos = atomicAdd(&g_c2_count, (unsigned)__popc(mask));
                pos = __shfl_sync(0xFFFFFFFFu, pos, leader);
                if (mid) {
                    unsigned p = pos + __popc(mask & ((1u << lane) - 1u));
                    if (p < CAP2) g_cand2[p] = cv;
                }
            }
        }
    }
    __threadfence();
    if (t == 0) {
        unsigned d = atomicAdd(&g_done3, 1u);
        s_last = (d == gridDim.x - 1u);
    }
    __syncthreads();
    if (!s_last) return;
    if (t == 0) g_done3 = 0u;
    if (work && bucket >= 0) {
        unsigned m2 = min(atomicAdd(&g_c2_count, 0u), CAP2);
        refine_body(out, bucket, g_rem, m2, sh, ssum, eqidx, misc);
    }
}

// ---------------------------------------------------------------------------
// K5: single-block exact fallback (only if g_need_full) + state cleanup.
__global__ void fallback_kernel(const float4* __restrict__ x4, int n4,
                                const float* __restrict__ x, int n,
                                const int* __restrict__ kptr, long long num_samples,
                                float* __restrict__ out) {
    __shared__ unsigned int sh[8192];
    __shared__ unsigned int ssum[1024];
    __shared__ unsigned int eqidx[EQ_CAP];
    __shared__ unsigned int misc[8];
    int t = threadIdx.x;
    if (g_need_full) {
        // full exact 4096-bin histogram of all positives
        for (int i = t; i < HIST_BINS; i += 1024) sh[i] = 0;
        __syncthreads();
        for (int i = t; i < n4; i += 1024) {
            float4 v = x4[i];
            if (v.x > 0.f) atomicAdd(&sh[__float_as_uint(v.x) >> 19], 1u);
            if (v.y > 0.f) atomicAdd(&sh[__float_as_uint(v.y) >> 19], 1u);
            if (v.z > 0.f) atomicAdd(&sh[__float_as_uint(v.z) >> 19], 1u);
            if (v.w > 0.f) atomicAdd(&sh[__float_as_uint(v.w) >> 19], 1u);
        }
        for (int t0 = n4 * 4 + t; t0 < n; t0 += 1024) {
            float v = x[t0];
            if (v > 0.f) atomicAdd(&sh[__float_as_uint(v) >> 19], 1u);
        }
        __syncthreads();
        if (t == 0) {
            long long n_keep = (long long)kptr[0] * num_samples;
            if (n_keep <= 0) { g_bucket = HIST_BINS; g_rem = 0; }
            else {
                long long cum = 0;
                int bkt = -1; unsigned rem = 0;
                for (int i = HIST_BINS - 1; i >= 0; --i) {
                    unsigned c = sh[i];
                    if (cum + (long long)c >= n_keep) {
                        bkt = i; rem = (unsigned)(n_keep - cum); break;
                    }
                    cum += c;
                }
                g_bucket = bkt; g_rem = rem;   // bkt==-1: keep all positives
            }
            g_c2_count = 0;
        }
        __syncthreads();
        int bucket = g_bucket;
        unsigned r = g_rem;
        if (bucket != HIST_BINS) {
            for (int i = t; i < n; i += 1024) {
                float s = x[i];
                if (s > 0.f) {
                    unsigned u = __float_as_uint(s);
                    int bin = (int)(u >> 19);
                    if (bucket == -1 || bin > bucket) out[i] = s;
                    else if (bin == bucket) {
                        unsigned p = atomicAdd(&g_c2_count, 1u);
                        if (p < CAP2)
                            g_cand2[p] = ((unsigned long long)u << 32) |
                                         (unsigned long long)(unsigned)i;
                    }
                }
            }
            __syncthreads();
            if (bucket >= 0) {
                unsigned m = min(atomicAdd(&g_c2_count, 0u), CAP2);
                refine_body(out, bucket, r, m, sh, ssum, eqidx, misc);
            }
        }
    }
    __syncthreads();
    if (t == 0) { g_need_full = 0; g_cand_count = 0; g_c2_count = 0; }
}

// ---------------------------------------------------------------------------
extern "C" void kernel_launch(void* const* d_in, const int* in_sizes, int n_in,
                              void* d_out, int out_size) {
    const float* x  = (const float*)d_in[0];
    const int*   kp = (const int*)d_in[1];
    int n = in_sizes[0];
    long long num_samples = (long long)n / 16384;  // last dim = 16384
    int n4 = n / 4;

    sample_kernel<<<SAMPLE_BLOCKS, 256>>>((const float4*)x, n4, n, kp, num_samples);

    int mb = (n4 + 511) / 512;
    if (mb < 1) mb = 1;
    int total_threads = mb * 256;
    main_kernel<<<mb, 256>>>((const float4*)x, (float4*)d_out, n4,
                             x, (float*)d_out, n, total_threads);

    candhist_kernel<<<CH_BLOCKS, 256>>>(kp, num_samples);
    scatter_kernel<<<SC_BLOCKS, 1024>>>((float*)d_out);
    fallback_kernel<<<1, 1024>>>((const float4*)x, n4, x, n, kp, num_samples,
                                 (float*)d_out);
}